// round 12
// baseline (speedup 1.0000x reference)
#include <cuda_runtime.h>
#include <cstdint>

#define EPSF 1e-6f
#define L2E  1.44269504088896340736f

constexpr int SI = 3000;
constexpr int SJ = 3000;
constexpr int NLINKS = 500000;
constexpr int BT = 256;
constexpr int GATHER_BLOCKS = (SI + BT - 1) / BT;   // 12
constexpr int IT = 2;                               // i's per block-term block
constexpr int NBI = SI / IT;                        // 1500
constexpr int K2_LINK = 296;                        // link blocks first (R3-proven layout)
constexpr int K2_TOTAL = K2_LINK + NBI;

// ---------------- device scratch (allocation-free) ----------------
__device__ float4 g_zi0[SI], g_zi1[SI];      // gathered zi rows, EPS pre-added
__device__ float  g_na[SI];                  // ||zi+eps||^2
__device__ float  g_bL[SI];                  // beta[si]*log2(e)
__device__ float4 g_q0[SJ], g_q1[SJ];        // gathered -2*zj rows
__device__ float2 g_nbgL[SJ];                // { ||zj||^2, gamma[sj]*log2(e) }
__device__ float  g_part_block[NBI];
__device__ float  g_part_links[K2_LINK];
__device__ int    g_ticket;

__device__ __forceinline__ float warp_sum(float v) {
    #pragma unroll
    for (int o = 16; o > 0; o >>= 1) v += __shfl_xor_sync(0xffffffffu, v, o);
    return v;
}
__device__ __forceinline__ float block_sum(float v) {
    __shared__ float w[BT / 32];
    v = warp_sum(v);
    if ((threadIdx.x & 31) == 0) w[threadIdx.x >> 5] = v;
    __syncthreads();
    if (threadIdx.x < BT / 32) {
        v = w[threadIdx.x];
        #pragma unroll
        for (int o = BT / 64; o > 0; o >>= 1) v += __shfl_xor_sync(0xffu, v, o);
    }
    return v;
}

// ================= kernel 1: gather + prescale + norms =================
__global__ __launch_bounds__(BT) void k1(const float* __restrict__ zi,
                                         const float* __restrict__ zj,
                                         const float* __restrict__ beta,
                                         const float* __restrict__ gamma,
                                         const int*   __restrict__ si,
                                         const int*   __restrict__ sj) {
    const int t = blockIdx.x * BT + threadIdx.x;
    if (t == 0) g_ticket = 0;
    if (t < SI) {
        const int i = si[t];
        float4 a0 = __ldg((const float4*)&zi[i * 8]);
        float4 a1 = __ldg((const float4*)&zi[i * 8 + 4]);
        a0.x += EPSF; a0.y += EPSF; a0.z += EPSF; a0.w += EPSF;
        a1.x += EPSF; a1.y += EPSF; a1.z += EPSF; a1.w += EPSF;
        g_zi0[t] = a0; g_zi1[t] = a1;
        float na = a0.x * a0.x;
        na = fmaf(a0.y, a0.y, na); na = fmaf(a0.z, a0.z, na); na = fmaf(a0.w, a0.w, na);
        na = fmaf(a1.x, a1.x, na); na = fmaf(a1.y, a1.y, na); na = fmaf(a1.z, a1.z, na);
        na = fmaf(a1.w, a1.w, na);
        g_na[t] = na;
        g_bL[t] = beta[i] * L2E;
    }
    if (t < SJ) {
        const int j = sj[t];
        const float4 b0 = __ldg((const float4*)&zj[j * 8]);
        const float4 b1 = __ldg((const float4*)&zj[j * 8 + 4]);
        float nb = b0.x * b0.x;
        nb = fmaf(b0.y, b0.y, nb); nb = fmaf(b0.z, b0.z, nb); nb = fmaf(b0.w, b0.w, nb);
        nb = fmaf(b1.x, b1.x, nb); nb = fmaf(b1.y, b1.y, nb); nb = fmaf(b1.z, b1.z, nb);
        nb = fmaf(b1.w, b1.w, nb);
        float4 q0, q1;
        q0.x = -2.0f * b0.x; q0.y = -2.0f * b0.y; q0.z = -2.0f * b0.z; q0.w = -2.0f * b0.w;
        q1.x = -2.0f * b1.x; q1.y = -2.0f * b1.y; q1.z = -2.0f * b1.z; q1.w = -2.0f * b1.w;
        g_q0[t] = q0; g_q1[t] = q1;
        g_nbgL[t] = make_float2(nb, gamma[j] * L2E);
    }
}

// ====== kernel 2: links (first) + block term (IT=2 norm-trick) + final reduce ======
__global__ __launch_bounds__(BT) void k2(const float* __restrict__ zi,
                                         const float* __restrict__ zj,
                                         const float* __restrict__ beta,
                                         const float* __restrict__ gamma,
                                         const int*   __restrict__ li,
                                         const int*   __restrict__ lj,
                                         float* __restrict__ out) {
    if (blockIdx.x < K2_LINK) {
        // ---- link term (memory-latency bound; exact subtraction form) ----
        const int b = blockIdx.x;
        const int stride = K2_LINK * BT;
        float acc = 0.0f;
        for (int e = b * BT + threadIdx.x; e < NLINKS; e += stride) {
            const int i = li[e];
            const int j = lj[e];
            const float4 a0 = __ldg((const float4*)&zi[i * 8]);
            const float4 a1 = __ldg((const float4*)&zi[i * 8 + 4]);
            const float4 b0 = __ldg((const float4*)&zj[j * 8]);
            const float4 b1 = __ldg((const float4*)&zj[j * 8 + 4]);
            float d0 = a0.x - b0.x + EPSF, d1 = a0.y - b0.y + EPSF;
            float d2 = a0.z - b0.z + EPSF, d3 = a0.w - b0.w + EPSF;
            float d4 = a1.x - b1.x + EPSF, d5 = a1.y - b1.y + EPSF;
            float d6 = a1.z - b1.z + EPSF, d7 = a1.w - b1.w + EPSF;
            float s = d0 * d0;
            s = fmaf(d1, d1, s); s = fmaf(d2, d2, s); s = fmaf(d3, d3, s);
            s = fmaf(d4, d4, s); s = fmaf(d5, d5, s); s = fmaf(d6, d6, s);
            s = fmaf(d7, d7, s);
            const float u = rsqrtf(s);
            acc += __ldg(&beta[i]) + __ldg(&gamma[j]) - s * u;
        }
        const float tot = block_sum(acc);
        if (threadIdx.x == 0) g_part_links[b] = tot;
    } else {
        // ---- sampled block term: 2 i's x all j, scalar norm-trick, sqrt.approx ----
        const int ib = (blockIdx.x - K2_LINK) * IT;

        const float4 A0a = g_zi0[ib],     A1a = g_zi1[ib];
        const float4 A0b = g_zi0[ib + 1], A1b = g_zi1[ib + 1];
        const float  naa = g_na[ib],      nab = g_na[ib + 1];
        const float  bLa = g_bL[ib],      bLb = g_bL[ib + 1];

        float acca = 0.0f, accb = 0.0f;

        #pragma unroll 2
        for (int j = threadIdx.x; j < SJ; j += BT) {
            const float4 q0 = g_q0[j];            // -2*zj
            const float4 q1 = g_q1[j];
            const float2 ng = g_nbgL[j];          // { nb, gL }

            // chain A: s = (na + nb) + a.(-2b)
            float sa = fmaf(A0a.x, q0.x, naa + ng.x);
            sa = fmaf(A0a.y, q0.y, sa); sa = fmaf(A0a.z, q0.z, sa); sa = fmaf(A0a.w, q0.w, sa);
            sa = fmaf(A1a.x, q1.x, sa); sa = fmaf(A1a.y, q1.y, sa); sa = fmaf(A1a.z, q1.z, sa);
            sa = fmaf(A1a.w, q1.w, sa);
            // chain B (independent)
            float sb = fmaf(A0b.x, q0.x, nab + ng.x);
            sb = fmaf(A0b.y, q0.y, sb); sb = fmaf(A0b.z, q0.z, sb); sb = fmaf(A0b.w, q0.w, sb);
            sb = fmaf(A1b.x, q1.x, sb); sb = fmaf(A1b.y, q1.y, sb); sb = fmaf(A1b.z, q1.z, sb);
            sb = fmaf(A1b.w, q1.w, sb);

            sa = fmaxf(sa, 1e-12f);
            sb = fmaxf(sb, 1e-12f);
            float da, db;
            asm("sqrt.approx.f32 %0, %1;" : "=f"(da) : "f"(sa));   // single MUFU
            asm("sqrt.approx.f32 %0, %1;" : "=f"(db) : "f"(sb));
            const float ta = fmaf(da, -L2E, bLa + ng.y);           // log2 domain
            const float tb = fmaf(db, -L2E, bLb + ng.y);
            float ea, eb;
            asm("ex2.approx.f32 %0, %1;" : "=f"(ea) : "f"(ta));    // MUFU.EX2
            asm("ex2.approx.f32 %0, %1;" : "=f"(eb) : "f"(tb));
            acca += ea;
            accb += eb;
        }
        const float tot = block_sum(acca + accb);
        if (threadIdx.x == 0) g_part_block[blockIdx.x - K2_LINK] = tot;
    }

    // ---- last-finishing block performs the deterministic final reduction ----
    __shared__ int isLast;
    __threadfence();                                   // release our partials
    if (threadIdx.x == 0) isLast = (atomicAdd(&g_ticket, 1) == K2_TOTAL - 1);
    __syncthreads();
    if (!isLast) return;
    __threadfence();                                   // acquire others' partials

    __shared__ double redB[BT], redL[BT];
    double sb = 0.0, sl = 0.0;
    for (int k = threadIdx.x; k < NBI; k += BT)     sb += (double)g_part_block[k];
    for (int k = threadIdx.x; k < K2_LINK; k += BT) sl += (double)g_part_links[k];
    redB[threadIdx.x] = sb;
    redL[threadIdx.x] = sl;
    __syncthreads();
    #pragma unroll
    for (int s2 = BT / 2; s2 > 0; s2 >>= 1) {
        if (threadIdx.x < s2) {
            redB[threadIdx.x] += redB[threadIdx.x + s2];
            redL[threadIdx.x] += redL[threadIdx.x + s2];
        }
        __syncthreads();
    }
    if (threadIdx.x == 0) out[0] = (float)(redL[0] - redB[0]);
}

extern "C" void kernel_launch(void* const* d_in, const int* in_sizes, int n_in,
                              void* d_out, int out_size) {
    const float* latent_zi = (const float*)d_in[0];
    const float* latent_zj = (const float*)d_in[1];
    const float* beta      = (const float*)d_in[2];
    const float* gamma     = (const float*)d_in[3];
    const int*   si        = (const int*)  d_in[4];
    const int*   sj        = (const int*)  d_in[5];
    const int*   li        = (const int*)  d_in[6];
    const int*   lj        = (const int*)  d_in[7];
    float* out = (float*)d_out;

    k1<<<GATHER_BLOCKS, BT>>>(latent_zi, latent_zj, beta, gamma, si, sj);
    k2<<<K2_TOTAL, BT>>>(latent_zi, latent_zj, beta, gamma, li, lj, out);
}